// round 9
// baseline (speedup 1.0000x reference)
#include <cuda_runtime.h>
#include <cuda_fp16.h>
#include <math_constants.h>
#include <cstdint>

#define DIM    1024
#define NHEAD  16
#define HDIM   64
#define BATCH  4
#define SEQ    2048
#define MTOT   (BATCH * SEQ)      // 8192

// Q pre-scale: 64^-0.5 * log2(e)  (softmax done in base 2)
#define QSCALE 0.18033688011112042f

// ---------------------------------------------------------------------------
// Scratch (fp16 activations/weights)
// ---------------------------------------------------------------------------
__device__ __half g_QKV[3 * MTOT * DIM];   // Q(pre-scaled),K,V
__device__ __half g_AO [MTOT * DIM];       // attention out
__device__ __half g_Wh [4 * DIM * DIM];    // fp16 Wq,Wk,Wv,Wo

// ---------------------------------------------------------------------------
// Helpers
// ---------------------------------------------------------------------------
__device__ __forceinline__ float ex2f(float x) {
    float y;
    asm("ex2.approx.f32 %0, %1;" : "=f"(y) : "f"(x));
    return y;
}

__device__ __forceinline__ uint32_t smem_u32(const void* p) {
    uint32_t a;
    asm("{ .reg .u64 t; cvta.to.shared.u64 t, %1; cvt.u32.u64 %0, t; }"
        : "=r"(a) : "l"(p));
    return a;
}

__device__ __forceinline__ unsigned h2bits(__half2 h) {
    return *reinterpret_cast<unsigned*>(&h);
}

__device__ __forceinline__ void mma_f16(float* c,
                                        unsigned a0, unsigned a1,
                                        unsigned a2, unsigned a3,
                                        unsigned b0, unsigned b1) {
    asm volatile(
        "mma.sync.aligned.m16n8k16.row.col.f32.f16.f16.f32 "
        "{%0,%1,%2,%3},{%4,%5,%6,%7},{%8,%9},{%0,%1,%2,%3};\n"
        : "+f"(c[0]), "+f"(c[1]), "+f"(c[2]), "+f"(c[3])
        : "r"(a0), "r"(a1), "r"(a2), "r"(a3), "r"(b0), "r"(b1));
}

#define LDSM_X4(r0, r1, r2, r3, addr)                                         \
    asm volatile("ldmatrix.sync.aligned.m8n8.x4.shared.b16 {%0,%1,%2,%3}, [%4];" \
                 : "=r"(r0), "=r"(r1), "=r"(r2), "=r"(r3) : "r"(addr))

#define LDSM_X4T(r0, r1, r2, r3, addr)                                        \
    asm volatile("ldmatrix.sync.aligned.m8n8.x4.trans.shared.b16 {%0,%1,%2,%3}, [%4];" \
                 : "=r"(r0), "=r"(r1), "=r"(r2), "=r"(r3) : "r"(addr))

#define CP_ASYNC16(dst, src) \
    asm volatile("cp.async.cg.shared.global [%0], [%1], 16;" \
                 :: "r"(dst), "l"(src) : "memory")
#define CP_COMMIT() asm volatile("cp.async.commit_group;" ::: "memory")
#define CP_WAIT(N)  asm volatile("cp.async.wait_group %0;" :: "n"(N) : "memory")

// ---------------------------------------------------------------------------
// Pre-pass: weights fp32 -> fp16 (weights reused 64x; x converts in-GEMM)
// ---------------------------------------------------------------------------
__global__ void cvt_w_k(const float4* __restrict__ w0, const float4* __restrict__ w1,
                        const float4* __restrict__ w2, const float4* __restrict__ w3,
                        __half2* __restrict__ dst)
{
    const float4* src = (blockIdx.y == 0) ? w0 : (blockIdx.y == 1) ? w1
                       : (blockIdx.y == 2) ? w2 : w3;
    __half2* d = dst + (size_t)blockIdx.y * (DIM * DIM / 2);
    const int n4 = DIM * DIM / 4;
    int i = blockIdx.x * blockDim.x + threadIdx.x;
    int stride = gridDim.x * blockDim.x;
    for (; i < n4; i += stride) {
        float4 v = src[i];
        d[2 * i]     = __floats2half2_rn(v.x, v.y);
        d[2 * i + 1] = __floats2half2_rn(v.z, v.w);
    }
}

// ---------------------------------------------------------------------------
// FP16 GEMM: C = A * W^T. Tile 128(M) x 256(N), BK=64, 3-stage pipeline.
// 512 threads / 16 warps, warp tile 32x64, m16n8k16 mma, ldmatrix frags.
// A32: A is fp32 in gmem, converted to fp16 during the smem fill (LDG+F2FP+STS,
// hidden under the tensor-bound mainloop). Otherwise A is fp16 via cp.async.
// ---------------------------------------------------------------------------
#define BK      64
#define NCH     (DIM / BK)              // 16
#define GROWB   144
#define A_STGB  (128 * GROWB)           // 18432
#define B_STGB  (256 * GROWB)           // 36864
#define STGB    (A_STGB + B_STGB)       // 55296
#define SMEM_GEMM (3 * STGB)            // 165888

template<bool A32, bool HALF_OUT, bool SCALEQ>
__global__ __launch_bounds__(512, 1)
void gemm_f16(const void* __restrict__ Abase,
              const __half* __restrict__ Wbase,
              void* __restrict__ Cvoid)
{
    extern __shared__ char smc[];
    const uint32_t sbase = smem_u32(smc);

    const int tid  = threadIdx.x;
    const int lane = tid & 31;
    const int warp = tid >> 5;           // 0..15
    const int wm   = warp & 3;
    const int wn   = warp >> 2;
    const int r    = lane >> 2;
    const int t    = lane & 3;
    const int m0   = blockIdx.y * 128;
    const int n0   = blockIdx.x * 256;

    const __half* W = Wbase + (size_t)blockIdx.z * DIM * DIM;

    float c[2][8][4];
    #pragma unroll
    for (int mi = 0; mi < 2; ++mi)
        #pragma unroll
        for (int ni = 0; ni < 8; ++ni)
            #pragma unroll
            for (int j = 0; j < 4; ++j) c[mi][ni][j] = 0.0f;

    const int arow  = ((lane >> 3) & 1) * 8 + (lane & 7);
    const int abyte = (lane >> 4) * 16;
    const int brow  = ((lane >> 4) & 1) * 8 + (lane & 7);
    const int bbyte = ((lane >> 3) & 1) * 16;
    const uint32_t aFrag = (uint32_t)((wm * 32 + arow) * GROWB + abyte);
    const uint32_t bFrag = (uint32_t)(A_STGB + (wn * 64 + brow) * GROWB + bbyte);

    auto load_stage = [&](int ch, int s) {
        const uint32_t as = sbase + s * STGB;
        const uint32_t bs = as + A_STGB;
        if (A32) {
            const float* Ab = (const float*)Abase + (size_t)m0 * DIM + ch * BK;
            #pragma unroll
            for (int p = 0; p < 2; ++p) {
                int slot = tid + p * 512;
                int row  = slot >> 3;
                int c8   = (slot & 7) * 8;
                const float4* src = reinterpret_cast<const float4*>(
                    Ab + (size_t)row * DIM + c8);
                float4 u = src[0], v = src[1];
                uint4 hh;
                hh.x = h2bits(__floats2half2_rn(u.x, u.y));
                hh.y = h2bits(__floats2half2_rn(u.z, u.w));
                hh.z = h2bits(__floats2half2_rn(v.x, v.y));
                hh.w = h2bits(__floats2half2_rn(v.z, v.w));
                *reinterpret_cast<uint4*>(smc + s * STGB + row * GROWB + c8 * 2) = hh;
            }
        } else {
            const __half* Ab = (const __half*)Abase + (size_t)m0 * DIM + ch * BK;
            #pragma unroll
            for (int p = 0; p < 2; ++p) {
                int slot = tid + p * 512;
                int row  = slot >> 3;
                int c8   = (slot & 7) * 8;
                CP_ASYNC16(as + row * GROWB + c8 * 2,
                           Ab + (size_t)row * DIM + c8);
            }
        }
        const __half* Wb = W + (size_t)n0 * DIM + ch * BK;
        #pragma unroll
        for (int p = 0; p < 4; ++p) {
            int slot = tid + p * 512;
            int row  = slot >> 3;
            int c8   = (slot & 7) * 8;
            CP_ASYNC16(bs + row * GROWB + c8 * 2,
                       Wb + (size_t)row * DIM + c8);
        }
        CP_COMMIT();
    };

    load_stage(0, 0);
    load_stage(1, 1);

    for (int ch = 0; ch < NCH; ++ch) {
        if (ch < NCH - 1) { CP_WAIT(1); } else { CP_WAIT(0); }
        __syncthreads();
        if (ch + 2 < NCH) load_stage(ch + 2, (ch + 2) % 3);

        const uint32_t stg = sbase + (ch % 3) * STGB;
        const uint32_t aB  = stg + aFrag;
        const uint32_t bB  = stg + bFrag;

        #pragma unroll
        for (int ks = 0; ks < 4; ++ks) {
            unsigned a[2][4], b[4][4];
            #pragma unroll
            for (int mi = 0; mi < 2; ++mi)
                LDSM_X4(a[mi][0], a[mi][1], a[mi][2], a[mi][3],
                        aB + mi * (16 * GROWB) + ks * 32);
            #pragma unroll
            for (int pi = 0; pi < 4; ++pi)
                LDSM_X4(b[pi][0], b[pi][1], b[pi][2], b[pi][3],
                        bB + pi * (16 * GROWB) + ks * 32);
            #pragma unroll
            for (int mi = 0; mi < 2; ++mi)
                #pragma unroll
                for (int pi = 0; pi < 4; ++pi) {
                    mma_f16(c[mi][2*pi],   a[mi][0], a[mi][1], a[mi][2], a[mi][3],
                            b[pi][0], b[pi][1]);
                    mma_f16(c[mi][2*pi+1], a[mi][0], a[mi][1], a[mi][2], a[mi][3],
                            b[pi][2], b[pi][3]);
                }
        }
    }

    const float sc = (SCALEQ && blockIdx.z == 0) ? QSCALE : 1.0f;
    #pragma unroll
    for (int mi = 0; mi < 2; ++mi) {
        #pragma unroll
        for (int ni = 0; ni < 8; ++ni) {
            int row = m0 + wm * 32 + mi * 16 + r;
            int col = n0 + wn * 64 + ni * 8 + 2 * t;
            float v0 = c[mi][ni][0] * sc, v1 = c[mi][ni][1] * sc;
            float v2 = c[mi][ni][2] * sc, v3 = c[mi][ni][3] * sc;
            if (HALF_OUT) {
                __half* C = (__half*)Cvoid + (size_t)blockIdx.z * MTOT * DIM;
                *reinterpret_cast<__half2*>(&C[(size_t)row * DIM + col]) =
                    __floats2half2_rn(v0, v1);
                *reinterpret_cast<__half2*>(&C[(size_t)(row + 8) * DIM + col]) =
                    __floats2half2_rn(v2, v3);
            } else {
                float* C = (float*)Cvoid;
                *reinterpret_cast<float2*>(&C[(size_t)row * DIM + col])       = make_float2(v0, v1);
                *reinterpret_cast<float2*>(&C[(size_t)(row + 8) * DIM + col]) = make_float2(v2, v3);
            }
        }
    }
}

// ---------------------------------------------------------------------------
// Flash attention, fp16, register-resident P, f16x2 softmax exp.
// Q-tile 128 (8 warps), K-tile 64, K/V double-buffered cp.async.
// ---------------------------------------------------------------------------
#define FROWB 144                               // 64 halves + 16B pad
#define QS_B  0
#define KS_B(s) (18432 + (s) * 9216)
#define VS_B(s) (36864 + (s) * 9216)
#define FL_SMEMB 55296

__global__ __launch_bounds__(256, 2)
void flash_f16(const __half* __restrict__ Q,
               const __half* __restrict__ K,
               const __half* __restrict__ V,
               __half* __restrict__ O)
{
    extern __shared__ char smc[];
    const uint32_t smb = smem_u32(smc);

    const int tid  = threadIdx.x;
    const int lane = tid & 31;
    const int warp = tid >> 5;            // 0..7
    const int r    = lane >> 2;
    const int t    = lane & 3;
    const int qt   = (gridDim.x - 1) - blockIdx.x;   // heavy first
    const int h    = blockIdx.y;
    const int b    = blockIdx.z;
    const int q0   = qt * 128;
    const size_t base = (size_t)b * SEQ * DIM + (size_t)h * HDIM;

    const int arow  = ((lane >> 3) & 1) * 8 + (lane & 7);
    const int abyte = (lane >> 4) * 16;
    const int brow  = ((lane >> 4) & 1) * 8 + (lane & 7);
    const int bbyte = ((lane >> 3) & 1) * 16;
    const uint32_t qFrag = smb + QS_B + (warp * 16 + arow) * FROWB + abyte;

    auto load_kv = [&](int kt, int s) {
        const __half* Kb = K + base + (size_t)(kt * 64) * DIM;
        const __half* Vb = V + base + (size_t)(kt * 64) * DIM;
        const uint32_t ks = smb + KS_B(s);
        const uint32_t vs = smb + VS_B(s);
        #pragma unroll
        for (int p = 0; p < 2; ++p) {
            int slot = tid + p * 256;
            int row  = slot >> 3;
            int c8   = (slot & 7) * 8;
            CP_ASYNC16(ks + row * FROWB + c8 * 2, Kb + (size_t)row * DIM + c8);
            CP_ASYNC16(vs + row * FROWB + c8 * 2, Vb + (size_t)row * DIM + c8);
        }
        CP_COMMIT();
    };

    load_kv(0, 0);

    #pragma unroll
    for (int p = 0; p < 4; ++p) {
        int slot = tid + p * 256;
        int row  = slot >> 3;
        int c8   = (slot & 7) * 8;
        uint4 v = *reinterpret_cast<const uint4*>(
            &Q[base + (size_t)(q0 + row) * DIM + c8]);
        *reinterpret_cast<uint4*>(smc + QS_B + row * FROWB + c8 * 2) = v;
    }
    __syncthreads();

    unsigned qa[4][4];
    #pragma unroll
    for (int ks = 0; ks < 4; ++ks)
        LDSM_X4(qa[ks][0], qa[ks][1], qa[ks][2], qa[ks][3], qFrag + ks * 32);

    float m_i[2] = {-CUDART_INF_F, -CUDART_INF_F};
    float l_i[2] = {0.0f, 0.0f};
    float o[8][4];
    #pragma unroll
    for (int ni = 0; ni < 8; ++ni)
        #pragma unroll
        for (int j = 0; j < 4; ++j) o[ni][j] = 0.0f;

    const int row_loc = warp * 16 + r;
    const int ktmax   = 2 * qt + 1;

    for (int kt = 0; kt <= ktmax; ++kt) {
        const int s  = kt & 1;
        const int k0 = kt * 64;

        CP_WAIT(0);
        __syncthreads();
        if (kt < ktmax) load_kv(kt + 1, s ^ 1);

        const uint32_t kFrag = smb + KS_B(s) + brow * FROWB + bbyte;
        const uint32_t vFrag = smb + VS_B(s) + arow * FROWB + abyte;

        const bool active = (k0 <= q0 + warp * 16 + 15);
        if (active) {
            // ---- S = Q K^T ----
            float sreg[8][4];
            #pragma unroll
            for (int ni = 0; ni < 8; ++ni)
                #pragma unroll
                for (int j = 0; j < 4; ++j) sreg[ni][j] = 0.0f;

            #pragma unroll
            for (int ks = 0; ks < 4; ++ks) {
                #pragma unroll
                for (int pi = 0; pi < 4; ++pi) {
                    unsigned b0, b1, b2, b3;
                    LDSM_X4(b0, b1, b2, b3, kFrag + pi * (16 * FROWB) + ks * 32);
                    mma_f16(sreg[2*pi],   qa[ks][0], qa[ks][1], qa[ks][2], qa[ks][3], b0, b1);
                    mma_f16(sreg[2*pi+1], qa[ks][0], qa[ks][1], qa[ks][2], qa[ks][3], b2, b3);
                }
            }

            // ---- causal mask (diagonal tiles only) ----
            if (k0 + 63 > q0 + warp * 16) {
                const int rg0 = q0 + row_loc;
                #pragma unroll
                for (int ni = 0; ni < 8; ++ni) {
                    int cg = k0 + ni * 8 + 2 * t;
                    if (cg     > rg0    ) sreg[ni][0] = -CUDART_INF_F;
                    if (cg + 1 > rg0    ) sreg[ni][1] = -CUDART_INF_F;
                    if (cg     > rg0 + 8) sreg[ni][2] = -CUDART_INF_F;
                    if (cg + 1 > rg0 + 8) sreg[ni][3] = -CUDART_INF_F;
                }
            }

            // ---- running max + rescale (fp32) ----
            float mnew[2], alpha[2];
            #pragma unroll
            for (int hh = 0; hh < 2; ++hh) {
                float mx = -CUDART_INF_F;
                #pragma unroll
                for (int ni = 0; ni < 8; ++ni)
                    mx = fmaxf(mx, fmaxf(sreg[ni][hh * 2], sreg[ni][hh * 2 + 1]));
                mx = fmaxf(mx, __shfl_xor_sync(0xffffffffu, mx, 1, 4));
                mx = fmaxf(mx, __shfl_xor_sync(0xffffffffu, mx, 2, 4));
                mnew[hh]  = fmaxf(m_i[hh], mx);
                alpha[hh] = ex2f(m_i[hh] - mnew[hh]);
                m_i[hh]   = mnew[hh];
                #pragma unroll
                for (int ni = 0; ni < 8; ++ni) {
                    o[ni][hh * 2]     *= alpha[hh];
                    o[ni][hh * 2 + 1] *= alpha[hh];
                }
            }

            // ---- p = 2^(s-m) computed directly in f16x2 -> A-fragments ----
            unsigned pa[4][4];
            float rs0 = 0.0f, rs1 = 0.0f;
            #pragma unroll
            for (int ni = 0; ni < 8; ++ni) {
                int ks = ni >> 1, ix = (ni & 1) << 1;
                __half2 e01 = h2exp2(__floats2half2_rn(
                    sreg[ni][0] - mnew[0], sreg[ni][1] - mnew[0]));
                __half2 e23 = h2exp2(__floats2half2_rn(
                    sreg[ni][2] - mnew[1], sreg[ni][3] - mnew[1]));
                pa[ks][ix]     = h2bits(e01);
                pa[ks][ix + 1] = h2bits(e23);
                float2 f01 = __half22float2(e01);
                float2 f23 = __half22float2(e23);
                rs0 += f01.x + f01.y;
                rs1 += f23.x + f23.y;
            }
            rs0 += __shfl_xor_sync(0xffffffffu, rs0, 1, 4);
            rs0 += __shfl_xor_sync(0xffffffffu, rs0, 2, 4);
            rs1 += __shfl_xor_sync(0xffffffffu, rs1, 1, 4);
            rs1 += __shfl_xor_sync(0xffffffffu, rs1, 2, 4);
            l_i[0] = l_i[0] * alpha[0] + rs0;
            l_i[1] = l_i[1] * alpha[1] + rs1;

            // ---- O += P V  (V B-frags via ldmatrix.trans from [k][d]) ----
            #pragma unroll
            for (int ks = 0; ks < 4; ++ks) {
                #pragma unroll
                for (int pi = 0; pi < 4; ++pi) {
                    unsigned b0, b1, b2, b3;
                    LDSM_X4T(b0, b1, b2, b3,
                             vFrag + ks * (16 * FROWB) + pi * 32);
                    mma_f16(o[2*pi],   pa[ks][0], pa[ks][1], pa[ks][2], pa[ks][3], b0, b1);
                    mma_f16(o[2*pi+1], pa[ks][0], pa[ks][1], pa[ks][2], pa[ks][3], b2, b3);
                }
            }
        }
        __syncthreads();
    }

    // ---- normalize + fp16 store ----
    #pragma unroll
    for (int hh = 0; hh < 2; ++hh) {
        float inv_l = 1.0f / l_i[hh];
        int row = q0 + row_loc + hh * 8;
        #pragma unroll
        for (int ni = 0; ni < 8; ++ni) {
            *reinterpret_cast<__half2*>(
                &O[base + (size_t)row * DIM + ni * 8 + 2 * t]) =
                __floats2half2_rn(o[ni][hh * 2] * inv_l, o[ni][hh * 2 + 1] * inv_l);
        }
    }
}

// ---------------------------------------------------------------------------
// Launch
// ---------------------------------------------------------------------------
extern "C" void kernel_launch(void* const* d_in, const int* in_sizes, int n_in,
                              void* d_out, int out_size)
{
    const float* x  = (const float*)d_in[0];
    const float* Wq = (const float*)d_in[2];
    const float* Wk = (const float*)d_in[3];
    const float* Wv = (const float*)d_in[4];
    const float* Wo = (const float*)d_in[5];
    float* out = (float*)d_out;

    __half *QKV, *AOd, *Wh;
    cudaGetSymbolAddress((void**)&QKV, g_QKV);
    cudaGetSymbolAddress((void**)&AOd, g_AO);
    cudaGetSymbolAddress((void**)&Wh,  g_Wh);

    static bool attr_set = false;
    if (!attr_set) {
        cudaFuncSetAttribute(flash_f16,
                             cudaFuncAttributeMaxDynamicSharedMemorySize, FL_SMEMB);
        cudaFuncSetAttribute((gemm_f16<true, true, true>),
                             cudaFuncAttributeMaxDynamicSharedMemorySize, SMEM_GEMM);
        cudaFuncSetAttribute((gemm_f16<false, false, false>),
                             cudaFuncAttributeMaxDynamicSharedMemorySize, SMEM_GEMM);
        attr_set = true;
    }

    cvt_w_k<<<dim3(128, 4), 256>>>((const float4*)Wq, (const float4*)Wk,
                                   (const float4*)Wv, (const float4*)Wo, (__half2*)Wh);

    // fused Q,K,V projections; A = fp32 x converted in-kernel; Q pre-scaled
    dim3 gQKV(DIM / 256, MTOT / 128, 3);   // (4, 64, 3)
    gemm_f16<true, true, true><<<gQKV, 512, SMEM_GEMM>>>(x, Wh, QKV);

    const __half* Qd = QKV;
    const __half* Kd = QKV + (size_t)MTOT * DIM;
    const __half* Vd = QKV + 2 * (size_t)MTOT * DIM;

    dim3 gF(SEQ / 128, NHEAD, BATCH);      // (16, 16, 4)
    flash_f16<<<gF, 256, FL_SMEMB>>>(Qd, Kd, Vd, AOd);

    dim3 gO(DIM / 256, MTOT / 128, 1);
    gemm_f16<false, false, false><<<gO, 512, SMEM_GEMM>>>(AOd, Wh + 3 * (size_t)DIM * DIM, out);
}

// round 10
// speedup vs baseline: 1.1205x; 1.1205x over previous
#include <cuda_runtime.h>
#include <cuda_fp16.h>
#include <math_constants.h>
#include <cstdint>

#define DIM    1024
#define NHEAD  16
#define HDIM   64
#define BATCH  4
#define SEQ    2048
#define MTOT   (BATCH * SEQ)      // 8192

// Q pre-scale: 64^-0.5 * log2(e)  (softmax done in base 2)
#define QSCALE 0.18033688011112042f

// ---------------------------------------------------------------------------
// Scratch (fp16 activations/weights)
// ---------------------------------------------------------------------------
__device__ __half g_QKV[3 * MTOT * DIM];   // Q(pre-scaled),K,V
__device__ __half g_AO [MTOT * DIM];       // attention out
__device__ __half g_Xh [MTOT * DIM];       // fp16 x
__device__ __half g_Wh [4 * DIM * DIM];    // fp16 Wq,Wk,Wv,Wo

// ---------------------------------------------------------------------------
// Helpers
// ---------------------------------------------------------------------------
__device__ __forceinline__ float ex2f(float x) {
    float y;
    asm("ex2.approx.f32 %0, %1;" : "=f"(y) : "f"(x));
    return y;
}

__device__ __forceinline__ uint32_t smem_u32(const void* p) {
    uint32_t a;
    asm("{ .reg .u64 t; cvta.to.shared.u64 t, %1; cvt.u32.u64 %0, t; }"
        : "=r"(a) : "l"(p));
    return a;
}

__device__ __forceinline__ unsigned h2bits(__half2 h) {
    return *reinterpret_cast<unsigned*>(&h);
}

__device__ __forceinline__ void mma_f16(float* c,
                                        unsigned a0, unsigned a1,
                                        unsigned a2, unsigned a3,
                                        unsigned b0, unsigned b1) {
    asm volatile(
        "mma.sync.aligned.m16n8k16.row.col.f32.f16.f16.f32 "
        "{%0,%1,%2,%3},{%4,%5,%6,%7},{%8,%9},{%0,%1,%2,%3};\n"
        : "+f"(c[0]), "+f"(c[1]), "+f"(c[2]), "+f"(c[3])
        : "r"(a0), "r"(a1), "r"(a2), "r"(a3), "r"(b0), "r"(b1));
}

#define LDSM_X4(r0, r1, r2, r3, addr)                                         \
    asm volatile("ldmatrix.sync.aligned.m8n8.x4.shared.b16 {%0,%1,%2,%3}, [%4];" \
                 : "=r"(r0), "=r"(r1), "=r"(r2), "=r"(r3) : "r"(addr))

#define LDSM_X4T(r0, r1, r2, r3, addr)                                        \
    asm volatile("ldmatrix.sync.aligned.m8n8.x4.trans.shared.b16 {%0,%1,%2,%3}, [%4];" \
                 : "=r"(r0), "=r"(r1), "=r"(r2), "=r"(r3) : "r"(addr))

#define CP_ASYNC16(dst, src) \
    asm volatile("cp.async.cg.shared.global [%0], [%1], 16;" \
                 :: "r"(dst), "l"(src) : "memory")
#define CP_COMMIT() asm volatile("cp.async.commit_group;" ::: "memory")
#define CP_WAIT(N)  asm volatile("cp.async.wait_group %0;" :: "n"(N) : "memory")

// ---------------------------------------------------------------------------
// Pre-pass: fp32 -> fp16
// ---------------------------------------------------------------------------
__global__ void cvt_x_k(const float4* __restrict__ src,
                        __half2* __restrict__ dst, int n4)
{
    int i = blockIdx.x * blockDim.x + threadIdx.x;
    int stride = gridDim.x * blockDim.x;
    for (; i < n4; i += stride) {
        float4 v = src[i];
        dst[2 * i]     = __floats2half2_rn(v.x, v.y);
        dst[2 * i + 1] = __floats2half2_rn(v.z, v.w);
    }
}

__global__ void cvt_w_k(const float4* __restrict__ w0, const float4* __restrict__ w1,
                        const float4* __restrict__ w2, const float4* __restrict__ w3,
                        __half2* __restrict__ dst)
{
    const float4* src = (blockIdx.y == 0) ? w0 : (blockIdx.y == 1) ? w1
                       : (blockIdx.y == 2) ? w2 : w3;
    __half2* d = dst + (size_t)blockIdx.y * (DIM * DIM / 2);
    const int n4 = DIM * DIM / 4;
    int i = blockIdx.x * blockDim.x + threadIdx.x;
    int stride = gridDim.x * blockDim.x;
    for (; i < n4; i += stride) {
        float4 v = src[i];
        d[2 * i]     = __floats2half2_rn(v.x, v.y);
        d[2 * i + 1] = __floats2half2_rn(v.z, v.w);
    }
}

// ---------------------------------------------------------------------------
// FP16 GEMM: C = A * W^T. Tile 128(M) x 128(N), BK=64, 3-stage cp.async.
// 256 threads / 8 warps, warp tile 32x64, 2 blocks/SM (independent barriers
// interleave -> issue slots filled while sibling block syncs).
// ---------------------------------------------------------------------------
#define BK      64
#define NCH     (DIM / BK)              // 16
#define GROWB   144
#define A_STGB  (128 * GROWB)           // 18432
#define STGB    (2 * A_STGB)            // 36864 (A + B)
#define SMEM_GEMM (3 * STGB)            // 110592

template<bool HALF_OUT, bool SCALEQ>
__global__ __launch_bounds__(256, 2)
void gemm_f16(const __half* __restrict__ Abase,
              const __half* __restrict__ Wbase,
              void* __restrict__ Cvoid)
{
    extern __shared__ char smc[];
    const uint32_t sbase = smem_u32(smc);

    const int tid  = threadIdx.x;
    const int lane = tid & 31;
    const int warp = tid >> 5;           // 0..7
    const int wm   = warp & 3;           // m offset wm*32
    const int wn   = warp >> 2;          // n offset wn*64
    const int r    = lane >> 2;
    const int t    = lane & 3;
    const int m0   = blockIdx.y * 128;
    const int n0   = blockIdx.x * 128;

    const __half* A = Abase;
    const __half* W = Wbase + (size_t)blockIdx.z * DIM * DIM;

    float c[2][8][4];
    #pragma unroll
    for (int mi = 0; mi < 2; ++mi)
        #pragma unroll
        for (int ni = 0; ni < 8; ++ni)
            #pragma unroll
            for (int j = 0; j < 4; ++j) c[mi][ni][j] = 0.0f;

    const int arow  = ((lane >> 3) & 1) * 8 + (lane & 7);
    const int abyte = (lane >> 4) * 16;
    const int brow  = ((lane >> 4) & 1) * 8 + (lane & 7);
    const int bbyte = ((lane >> 3) & 1) * 16;
    const uint32_t aFrag = (uint32_t)((wm * 32 + arow) * GROWB + abyte);
    const uint32_t bFrag = (uint32_t)(A_STGB + (wn * 64 + brow) * GROWB + bbyte);

    auto load_stage = [&](int ch, int s) {
        const __half* Ab = A + (size_t)m0 * DIM + ch * BK;
        const __half* Wb = W + (size_t)n0 * DIM + ch * BK;
        const uint32_t as = sbase + s * STGB;
        const uint32_t bs = as + A_STGB;
        #pragma unroll
        for (int p = 0; p < 4; ++p) {             // A: 1024 x 16B
            int slot = tid + p * 256;
            int row  = slot >> 3;
            int c8   = (slot & 7) * 8;
            CP_ASYNC16(as + row * GROWB + c8 * 2,
                       Ab + (size_t)row * DIM + c8);
        }
        #pragma unroll
        for (int p = 0; p < 4; ++p) {             // B: 1024 x 16B
            int slot = tid + p * 256;
            int row  = slot >> 3;
            int c8   = (slot & 7) * 8;
            CP_ASYNC16(bs + row * GROWB + c8 * 2,
                       Wb + (size_t)row * DIM + c8);
        }
        CP_COMMIT();
    };

    load_stage(0, 0);
    load_stage(1, 1);

    for (int ch = 0; ch < NCH; ++ch) {
        if (ch < NCH - 1) { CP_WAIT(1); } else { CP_WAIT(0); }
        __syncthreads();
        if (ch + 2 < NCH) load_stage(ch + 2, (ch + 2) % 3);

        const uint32_t stg = sbase + (ch % 3) * STGB;
        const uint32_t aB  = stg + aFrag;
        const uint32_t bB  = stg + bFrag;

        #pragma unroll
        for (int ks = 0; ks < 4; ++ks) {
            unsigned a[2][4], b[4][4];
            #pragma unroll
            for (int mi = 0; mi < 2; ++mi)
                LDSM_X4(a[mi][0], a[mi][1], a[mi][2], a[mi][3],
                        aB + mi * (16 * GROWB) + ks * 32);
            #pragma unroll
            for (int pi = 0; pi < 4; ++pi)
                LDSM_X4(b[pi][0], b[pi][1], b[pi][2], b[pi][3],
                        bB + pi * (16 * GROWB) + ks * 32);
            #pragma unroll
            for (int mi = 0; mi < 2; ++mi)
                #pragma unroll
                for (int pi = 0; pi < 4; ++pi) {
                    mma_f16(c[mi][2*pi],   a[mi][0], a[mi][1], a[mi][2], a[mi][3],
                            b[pi][0], b[pi][1]);
                    mma_f16(c[mi][2*pi+1], a[mi][0], a[mi][1], a[mi][2], a[mi][3],
                            b[pi][2], b[pi][3]);
                }
        }
    }

    const float sc = (SCALEQ && blockIdx.z == 0) ? QSCALE : 1.0f;
    #pragma unroll
    for (int mi = 0; mi < 2; ++mi) {
        #pragma unroll
        for (int ni = 0; ni < 8; ++ni) {
            int row = m0 + wm * 32 + mi * 16 + r;
            int col = n0 + wn * 64 + ni * 8 + 2 * t;
            float v0 = c[mi][ni][0] * sc, v1 = c[mi][ni][1] * sc;
            float v2 = c[mi][ni][2] * sc, v3 = c[mi][ni][3] * sc;
            if (HALF_OUT) {
                __half* C = (__half*)Cvoid + (size_t)blockIdx.z * MTOT * DIM;
                *reinterpret_cast<__half2*>(&C[(size_t)row * DIM + col]) =
                    __floats2half2_rn(v0, v1);
                *reinterpret_cast<__half2*>(&C[(size_t)(row + 8) * DIM + col]) =
                    __floats2half2_rn(v2, v3);
            } else {
                float* C = (float*)Cvoid;
                *reinterpret_cast<float2*>(&C[(size_t)row * DIM + col])       = make_float2(v0, v1);
                *reinterpret_cast<float2*>(&C[(size_t)(row + 8) * DIM + col]) = make_float2(v2, v3);
            }
        }
    }
}

// ---------------------------------------------------------------------------
// Flash attention, fp16, register-resident P, f16x2 softmax exp.
// Q-tile 128 (8 warps), K-tile 64, K/V double-buffered cp.async.
// ---------------------------------------------------------------------------
#define FROWB 144                               // 64 halves + 16B pad
#define QS_B  0
#define KS_B(s) (18432 + (s) * 9216)
#define VS_B(s) (36864 + (s) * 9216)
#define FL_SMEMB 55296

__global__ __launch_bounds__(256, 2)
void flash_f16(const __half* __restrict__ Q,
               const __half* __restrict__ K,
               const __half* __restrict__ V,
               __half* __restrict__ O)
{
    extern __shared__ char smc[];
    const uint32_t smb = smem_u32(smc);

    const int tid  = threadIdx.x;
    const int lane = tid & 31;
    const int warp = tid >> 5;            // 0..7
    const int r    = lane >> 2;
    const int t    = lane & 3;
    const int qt   = (gridDim.x - 1) - blockIdx.x;   // heavy first
    const int h    = blockIdx.y;
    const int b    = blockIdx.z;
    const int q0   = qt * 128;
    const size_t base = (size_t)b * SEQ * DIM + (size_t)h * HDIM;

    const int arow  = ((lane >> 3) & 1) * 8 + (lane & 7);
    const int abyte = (lane >> 4) * 16;
    const int brow  = ((lane >> 4) & 1) * 8 + (lane & 7);
    const int bbyte = ((lane >> 3) & 1) * 16;
    const uint32_t qFrag = smb + QS_B + (warp * 16 + arow) * FROWB + abyte;

    auto load_kv = [&](int kt, int s) {
        const __half* Kb = K + base + (size_t)(kt * 64) * DIM;
        const __half* Vb = V + base + (size_t)(kt * 64) * DIM;
        const uint32_t ks = smb + KS_B(s);
        const uint32_t vs = smb + VS_B(s);
        #pragma unroll
        for (int p = 0; p < 2; ++p) {
            int slot = tid + p * 256;
            int row  = slot >> 3;
            int c8   = (slot & 7) * 8;
            CP_ASYNC16(ks + row * FROWB + c8 * 2, Kb + (size_t)row * DIM + c8);
            CP_ASYNC16(vs + row * FROWB + c8 * 2, Vb + (size_t)row * DIM + c8);
        }
        CP_COMMIT();
    };

    load_kv(0, 0);

    #pragma unroll
    for (int p = 0; p < 4; ++p) {
        int slot = tid + p * 256;
        int row  = slot >> 3;
        int c8   = (slot & 7) * 8;
        uint4 v = *reinterpret_cast<const uint4*>(
            &Q[base + (size_t)(q0 + row) * DIM + c8]);
        *reinterpret_cast<uint4*>(smc + QS_B + row * FROWB + c8 * 2) = v;
    }
    __syncthreads();

    unsigned qa[4][4];
    #pragma unroll
    for (int ks = 0; ks < 4; ++ks)
        LDSM_X4(qa[ks][0], qa[ks][1], qa[ks][2], qa[ks][3], qFrag + ks * 32);

    float m_i[2] = {-CUDART_INF_F, -CUDART_INF_F};
    float l_i[2] = {0.0f, 0.0f};
    float o[8][4];
    #pragma unroll
    for (int ni = 0; ni < 8; ++ni)
        #pragma unroll
        for (int j = 0; j < 4; ++j) o[ni][j] = 0.0f;

    const int row_loc = warp * 16 + r;
    const int ktmax   = 2 * qt + 1;

    for (int kt = 0; kt <= ktmax; ++kt) {
        const int s  = kt & 1;
        const int k0 = kt * 64;

        CP_WAIT(0);
        __syncthreads();
        if (kt < ktmax) load_kv(kt + 1, s ^ 1);

        const uint32_t kFrag = smb + KS_B(s) + brow * FROWB + bbyte;
        const uint32_t vFrag = smb + VS_B(s) + arow * FROWB + abyte;

        const bool active = (k0 <= q0 + warp * 16 + 15);
        if (active) {
            // ---- S = Q K^T ----
            float sreg[8][4];
            #pragma unroll
            for (int ni = 0; ni < 8; ++ni)
                #pragma unroll
                for (int j = 0; j < 4; ++j) sreg[ni][j] = 0.0f;

            #pragma unroll
            for (int ks = 0; ks < 4; ++ks) {
                #pragma unroll
                for (int pi = 0; pi < 4; ++pi) {
                    unsigned b0, b1, b2, b3;
                    LDSM_X4(b0, b1, b2, b3, kFrag + pi * (16 * FROWB) + ks * 32);
                    mma_f16(sreg[2*pi],   qa[ks][0], qa[ks][1], qa[ks][2], qa[ks][3], b0, b1);
                    mma_f16(sreg[2*pi+1], qa[ks][0], qa[ks][1], qa[ks][2], qa[ks][3], b2, b3);
                }
            }

            // ---- causal mask (diagonal tiles only) ----
            if (k0 + 63 > q0 + warp * 16) {
                const int rg0 = q0 + row_loc;
                #pragma unroll
                for (int ni = 0; ni < 8; ++ni) {
                    int cg = k0 + ni * 8 + 2 * t;
                    if (cg     > rg0    ) sreg[ni][0] = -CUDART_INF_F;
                    if (cg + 1 > rg0    ) sreg[ni][1] = -CUDART_INF_F;
                    if (cg     > rg0 + 8) sreg[ni][2] = -CUDART_INF_F;
                    if (cg + 1 > rg0 + 8) sreg[ni][3] = -CUDART_INF_F;
                }
            }

            // ---- running max + rescale (fp32) ----
            float mnew[2], alpha[2];
            #pragma unroll
            for (int hh = 0; hh < 2; ++hh) {
                float mx = -CUDART_INF_F;
                #pragma unroll
                for (int ni = 0; ni < 8; ++ni)
                    mx = fmaxf(mx, fmaxf(sreg[ni][hh * 2], sreg[ni][hh * 2 + 1]));
                mx = fmaxf(mx, __shfl_xor_sync(0xffffffffu, mx, 1, 4));
                mx = fmaxf(mx, __shfl_xor_sync(0xffffffffu, mx, 2, 4));
                mnew[hh]  = fmaxf(m_i[hh], mx);
                alpha[hh] = ex2f(m_i[hh] - mnew[hh]);
                m_i[hh]   = mnew[hh];
                #pragma unroll
                for (int ni = 0; ni < 8; ++ni) {
                    o[ni][hh * 2]     *= alpha[hh];
                    o[ni][hh * 2 + 1] *= alpha[hh];
                }
            }

            // ---- p = 2^(s-m) computed directly in f16x2 -> A-fragments ----
            unsigned pa[4][4];
            float rs0 = 0.0f, rs1 = 0.0f;
            #pragma unroll
            for (int ni = 0; ni < 8; ++ni) {
                int ks = ni >> 1, ix = (ni & 1) << 1;
                __half2 e01 = h2exp2(__floats2half2_rn(
                    sreg[ni][0] - mnew[0], sreg[ni][1] - mnew[0]));
                __half2 e23 = h2exp2(__floats2half2_rn(
                    sreg[ni][2] - mnew[1], sreg[ni][3] - mnew[1]));
                pa[ks][ix]     = h2bits(e01);
                pa[ks][ix + 1] = h2bits(e23);
                float2 f01 = __half22float2(e01);
                float2 f23 = __half22float2(e23);
                rs0 += f01.x + f01.y;
                rs1 += f23.x + f23.y;
            }
            rs0 += __shfl_xor_sync(0xffffffffu, rs0, 1, 4);
            rs0 += __shfl_xor_sync(0xffffffffu, rs0, 2, 4);
            rs1 += __shfl_xor_sync(0xffffffffu, rs1, 1, 4);
            rs1 += __shfl_xor_sync(0xffffffffu, rs1, 2, 4);
            l_i[0] = l_i[0] * alpha[0] + rs0;
            l_i[1] = l_i[1] * alpha[1] + rs1;

            // ---- O += P V  (V B-frags via ldmatrix.trans from [k][d]) ----
            #pragma unroll
            for (int ks = 0; ks < 4; ++ks) {
                #pragma unroll
                for (int pi = 0; pi < 4; ++pi) {
                    unsigned b0, b1, b2, b3;
                    LDSM_X4T(b0, b1, b2, b3,
                             vFrag + ks * (16 * FROWB) + pi * 32);
                    mma_f16(o[2*pi],   pa[ks][0], pa[ks][1], pa[ks][2], pa[ks][3], b0, b1);
                    mma_f16(o[2*pi+1], pa[ks][0], pa[ks][1], pa[ks][2], pa[ks][3], b2, b3);
                }
            }
        }
        __syncthreads();
    }

    // ---- normalize + fp16 store ----
    #pragma unroll
    for (int hh = 0; hh < 2; ++hh) {
        float inv_l = 1.0f / l_i[hh];
        int row = q0 + row_loc + hh * 8;
        #pragma unroll
        for (int ni = 0; ni < 8; ++ni) {
            *reinterpret_cast<__half2*>(
                &O[base + (size_t)row * DIM + ni * 8 + 2 * t]) =
                __floats2half2_rn(o[ni][hh * 2] * inv_l, o[ni][hh * 2 + 1] * inv_l);
        }
    }
}

// ---------------------------------------------------------------------------
// Launch
// ---------------------------------------------------------------------------
extern "C" void kernel_launch(void* const* d_in, const int* in_sizes, int n_in,
                              void* d_out, int out_size)
{
    const float* x  = (const float*)d_in[0];
    const float* Wq = (const float*)d_in[2];
    const float* Wk = (const float*)d_in[3];
    const float* Wv = (const float*)d_in[4];
    const float* Wo = (const float*)d_in[5];
    float* out = (float*)d_out;

    __half *QKV, *AOd, *Xh, *Wh;
    cudaGetSymbolAddress((void**)&QKV, g_QKV);
    cudaGetSymbolAddress((void**)&AOd, g_AO);
    cudaGetSymbolAddress((void**)&Xh,  g_Xh);
    cudaGetSymbolAddress((void**)&Wh,  g_Wh);

    static bool attr_set = false;
    if (!attr_set) {
        cudaFuncSetAttribute(flash_f16,
                             cudaFuncAttributeMaxDynamicSharedMemorySize, FL_SMEMB);
        cudaFuncSetAttribute((gemm_f16<true, true>),
                             cudaFuncAttributeMaxDynamicSharedMemorySize, SMEM_GEMM);
        cudaFuncSetAttribute((gemm_f16<false, false>),
                             cudaFuncAttributeMaxDynamicSharedMemorySize, SMEM_GEMM);
        attr_set = true;
    }

    cvt_x_k<<<1024, 256>>>((const float4*)x, (__half2*)Xh, MTOT * DIM / 4);
    cvt_w_k<<<dim3(128, 4), 256>>>((const float4*)Wq, (const float4*)Wk,
                                   (const float4*)Wv, (const float4*)Wo, (__half2*)Wh);

    // fused Q,K,V projections; Q pre-scaled by 0.125*log2(e)
    dim3 gQKV(DIM / 128, MTOT / 128, 3);   // (8, 64, 3)
    gemm_f16<true, true><<<gQKV, 256, SMEM_GEMM>>>(Xh, Wh, QKV);

    const __half* Qd = QKV;
    const __half* Kd = QKV + (size_t)MTOT * DIM;
    const __half* Vd = QKV + 2 * (size_t)MTOT * DIM;

    dim3 gF(SEQ / 128, NHEAD, BATCH);      // (16, 16, 4)
    flash_f16<<<gF, 256, FL_SMEMB>>>(Qd, Kd, Vd, AOd);

    dim3 gO(DIM / 128, MTOT / 128, 1);     // (8, 64, 1)
    gemm_f16<false, false><<<gO, 256, SMEM_GEMM>>>(AOd, Wh + 3 * (size_t)DIM * DIM, out);
}

// round 11
// speedup vs baseline: 1.1505x; 1.0268x over previous
#include <cuda_runtime.h>
#include <cuda_fp16.h>
#include <math_constants.h>
#include <cstdint>

#define DIM    1024
#define NHEAD  16
#define HDIM   64
#define BATCH  4
#define SEQ    2048
#define MTOT   (BATCH * SEQ)      // 8192

// Q pre-scale: 64^-0.5 * log2(e)  (softmax done in base 2)
#define QSCALE 0.18033688011112042f

// ---------------------------------------------------------------------------
// Scratch (fp16 activations/weights)
// ---------------------------------------------------------------------------
__device__ __half g_QKV[3 * MTOT * DIM];   // Q(pre-scaled),K,V
__device__ __half g_AO [MTOT * DIM];       // attention out
__device__ __half g_Xh [MTOT * DIM];       // fp16 x
__device__ __half g_Wh [4 * DIM * DIM];    // fp16 Wq,Wk,Wv,Wo

// ---------------------------------------------------------------------------
// Helpers
// ---------------------------------------------------------------------------
__device__ __forceinline__ float ex2f(float x) {
    float y;
    asm("ex2.approx.f32 %0, %1;" : "=f"(y) : "f"(x));
    return y;
}

__device__ __forceinline__ uint32_t smem_u32(const void* p) {
    uint32_t a;
    asm("{ .reg .u64 t; cvta.to.shared.u64 t, %1; cvt.u32.u64 %0, t; }"
        : "=r"(a) : "l"(p));
    return a;
}

__device__ __forceinline__ unsigned pack_h2(float lo, float hi) {
    __half2 h = __floats2half2_rn(lo, hi);
    return *reinterpret_cast<unsigned*>(&h);
}

__device__ __forceinline__ void mma_f16(float* c,
                                        unsigned a0, unsigned a1,
                                        unsigned a2, unsigned a3,
                                        unsigned b0, unsigned b1) {
    asm volatile(
        "mma.sync.aligned.m16n8k16.row.col.f32.f16.f16.f32 "
        "{%0,%1,%2,%3},{%4,%5,%6,%7},{%8,%9},{%0,%1,%2,%3};\n"
        : "+f"(c[0]), "+f"(c[1]), "+f"(c[2]), "+f"(c[3])
        : "r"(a0), "r"(a1), "r"(a2), "r"(a3), "r"(b0), "r"(b1));
}

#define LDSM_X4(r0, r1, r2, r3, addr)                                         \
    asm volatile("ldmatrix.sync.aligned.m8n8.x4.shared.b16 {%0,%1,%2,%3}, [%4];" \
                 : "=r"(r0), "=r"(r1), "=r"(r2), "=r"(r3) : "r"(addr))

#define LDSM_X4T(r0, r1, r2, r3, addr)                                        \
    asm volatile("ldmatrix.sync.aligned.m8n8.x4.trans.shared.b16 {%0,%1,%2,%3}, [%4];" \
                 : "=r"(r0), "=r"(r1), "=r"(r2), "=r"(r3) : "r"(addr))

#define CP_ASYNC16(dst, src) \
    asm volatile("cp.async.cg.shared.global [%0], [%1], 16;" \
                 :: "r"(dst), "l"(src) : "memory")
#define CP_COMMIT() asm volatile("cp.async.commit_group;" ::: "memory")
#define CP_WAIT(N)  asm volatile("cp.async.wait_group %0;" :: "n"(N) : "memory")

// ---------------------------------------------------------------------------
// Pre-pass: fp32 -> fp16
// ---------------------------------------------------------------------------
__global__ void cvt_x_k(const float4* __restrict__ src,
                        __half2* __restrict__ dst, int n4)
{
    int i = blockIdx.x * blockDim.x + threadIdx.x;
    int stride = gridDim.x * blockDim.x;
    for (; i < n4; i += stride) {
        float4 v = src[i];
        dst[2 * i]     = __floats2half2_rn(v.x, v.y);
        dst[2 * i + 1] = __floats2half2_rn(v.z, v.w);
    }
}

__global__ void cvt_w_k(const float4* __restrict__ w0, const float4* __restrict__ w1,
                        const float4* __restrict__ w2, const float4* __restrict__ w3,
                        __half2* __restrict__ dst)
{
    const float4* src = (blockIdx.y == 0) ? w0 : (blockIdx.y == 1) ? w1
                       : (blockIdx.y == 2) ? w2 : w3;
    __half2* d = dst + (size_t)blockIdx.y * (DIM * DIM / 2);
    const int n4 = DIM * DIM / 4;
    int i = blockIdx.x * blockDim.x + threadIdx.x;
    int stride = gridDim.x * blockDim.x;
    for (; i < n4; i += stride) {
        float4 v = src[i];
        d[2 * i]     = __floats2half2_rn(v.x, v.y);
        d[2 * i + 1] = __floats2half2_rn(v.z, v.w);
    }
}

// ---------------------------------------------------------------------------
// FP16 GEMM: C = A * W^T. Tile 128(M) x 128(N), BK=64, 3-stage cp.async.
// 256 threads / 8 warps, warp tile 32x64, 2 blocks/SM (independent barriers
// interleave -> issue slots filled while sibling block syncs).
// ---------------------------------------------------------------------------
#define BK      64
#define NCH     (DIM / BK)              // 16
#define GROWB   144
#define A_STGB  (128 * GROWB)           // 18432
#define STGB    (2 * A_STGB)            // 36864 (A + B)
#define SMEM_GEMM (3 * STGB)            // 110592

template<bool HALF_OUT, bool SCALEQ>
__global__ __launch_bounds__(256, 2)
void gemm_f16(const __half* __restrict__ Abase,
              const __half* __restrict__ Wbase,
              void* __restrict__ Cvoid)
{
    extern __shared__ char smc[];
    const uint32_t sbase = smem_u32(smc);

    const int tid  = threadIdx.x;
    const int lane = tid & 31;
    const int warp = tid >> 5;           // 0..7
    const int wm   = warp & 3;           // m offset wm*32
    const int wn   = warp >> 2;          // n offset wn*64
    const int r    = lane >> 2;
    const int t    = lane & 3;
    const int m0   = blockIdx.y * 128;
    const int n0   = blockIdx.x * 128;

    const __half* A = Abase;
    const __half* W = Wbase + (size_t)blockIdx.z * DIM * DIM;

    float c[2][8][4];
    #pragma unroll
    for (int mi = 0; mi < 2; ++mi)
        #pragma unroll
        for (int ni = 0; ni < 8; ++ni)
            #pragma unroll
            for (int j = 0; j < 4; ++j) c[mi][ni][j] = 0.0f;

    const int arow  = ((lane >> 3) & 1) * 8 + (lane & 7);
    const int abyte = (lane >> 4) * 16;
    const int brow  = ((lane >> 4) & 1) * 8 + (lane & 7);
    const int bbyte = ((lane >> 3) & 1) * 16;
    const uint32_t aFrag = (uint32_t)((wm * 32 + arow) * GROWB + abyte);
    const uint32_t bFrag = (uint32_t)(A_STGB + (wn * 64 + brow) * GROWB + bbyte);

    auto load_stage = [&](int ch, int s) {
        const __half* Ab = A + (size_t)m0 * DIM + ch * BK;
        const __half* Wb = W + (size_t)n0 * DIM + ch * BK;
        const uint32_t as = sbase + s * STGB;
        const uint32_t bs = as + A_STGB;
        #pragma unroll
        for (int p = 0; p < 4; ++p) {             // A: 1024 x 16B
            int slot = tid + p * 256;
            int row  = slot >> 3;
            int c8   = (slot & 7) * 8;
            CP_ASYNC16(as + row * GROWB + c8 * 2,
                       Ab + (size_t)row * DIM + c8);
        }
        #pragma unroll
        for (int p = 0; p < 4; ++p) {             // B: 1024 x 16B
            int slot = tid + p * 256;
            int row  = slot >> 3;
            int c8   = (slot & 7) * 8;
            CP_ASYNC16(bs + row * GROWB + c8 * 2,
                       Wb + (size_t)row * DIM + c8);
        }
        CP_COMMIT();
    };

    load_stage(0, 0);
    load_stage(1, 1);

    for (int ch = 0; ch < NCH; ++ch) {
        if (ch < NCH - 1) { CP_WAIT(1); } else { CP_WAIT(0); }
        __syncthreads();
        if (ch + 2 < NCH) load_stage(ch + 2, (ch + 2) % 3);

        const uint32_t stg = sbase + (ch % 3) * STGB;
        const uint32_t aB  = stg + aFrag;
        const uint32_t bB  = stg + bFrag;

        #pragma unroll
        for (int ks = 0; ks < 4; ++ks) {
            unsigned a[2][4], b[4][4];
            #pragma unroll
            for (int mi = 0; mi < 2; ++mi)
                LDSM_X4(a[mi][0], a[mi][1], a[mi][2], a[mi][3],
                        aB + mi * (16 * GROWB) + ks * 32);
            #pragma unroll
            for (int pi = 0; pi < 4; ++pi)
                LDSM_X4(b[pi][0], b[pi][1], b[pi][2], b[pi][3],
                        bB + pi * (16 * GROWB) + ks * 32);
            #pragma unroll
            for (int mi = 0; mi < 2; ++mi)
                #pragma unroll
                for (int pi = 0; pi < 4; ++pi) {
                    mma_f16(c[mi][2*pi],   a[mi][0], a[mi][1], a[mi][2], a[mi][3],
                            b[pi][0], b[pi][1]);
                    mma_f16(c[mi][2*pi+1], a[mi][0], a[mi][1], a[mi][2], a[mi][3],
                            b[pi][2], b[pi][3]);
                }
        }
    }

    const float sc = (SCALEQ && blockIdx.z == 0) ? QSCALE : 1.0f;
    #pragma unroll
    for (int mi = 0; mi < 2; ++mi) {
        #pragma unroll
        for (int ni = 0; ni < 8; ++ni) {
            int row = m0 + wm * 32 + mi * 16 + r;
            int col = n0 + wn * 64 + ni * 8 + 2 * t;
            float v0 = c[mi][ni][0] * sc, v1 = c[mi][ni][1] * sc;
            float v2 = c[mi][ni][2] * sc, v3 = c[mi][ni][3] * sc;
            if (HALF_OUT) {
                __half* C = (__half*)Cvoid + (size_t)blockIdx.z * MTOT * DIM;
                *reinterpret_cast<__half2*>(&C[(size_t)row * DIM + col]) =
                    __floats2half2_rn(v0, v1);
                *reinterpret_cast<__half2*>(&C[(size_t)(row + 8) * DIM + col]) =
                    __floats2half2_rn(v2, v3);
            } else {
                float* C = (float*)Cvoid;
                *reinterpret_cast<float2*>(&C[(size_t)row * DIM + col])       = make_float2(v0, v1);
                *reinterpret_cast<float2*>(&C[(size_t)(row + 8) * DIM + col]) = make_float2(v2, v3);
            }
        }
    }
}

// ---------------------------------------------------------------------------
// Flash attention, fp16, register-resident P, fp32-ex2 softmax (R8-proven).
// Q-tile 128 (8 warps), K-tile 64, K/V double-buffered cp.async.
// Single barrier per iteration (tail sync removed: top-of-iter sync already
// orders all reads of buffer 1-s before the next load into 1-s).
// ---------------------------------------------------------------------------
#define FROWB 144                               // 64 halves + 16B pad
#define QS_B  0
#define KS_B(s) (18432 + (s) * 9216)
#define VS_B(s) (36864 + (s) * 9216)
#define FL_SMEMB 55296

__global__ __launch_bounds__(256, 2)
void flash_f16(const __half* __restrict__ Q,
               const __half* __restrict__ K,
               const __half* __restrict__ V,
               __half* __restrict__ O)
{
    extern __shared__ char smc[];
    const uint32_t smb = smem_u32(smc);

    const int tid  = threadIdx.x;
    const int lane = tid & 31;
    const int warp = tid >> 5;            // 0..7
    const int r    = lane >> 2;
    const int t    = lane & 3;
    const int qt   = (gridDim.x - 1) - blockIdx.x;   // heavy first
    const int h    = blockIdx.y;
    const int b    = blockIdx.z;
    const int q0   = qt * 128;
    const size_t base = (size_t)b * SEQ * DIM + (size_t)h * HDIM;

    const int arow  = ((lane >> 3) & 1) * 8 + (lane & 7);
    const int abyte = (lane >> 4) * 16;
    const int brow  = ((lane >> 4) & 1) * 8 + (lane & 7);
    const int bbyte = ((lane >> 3) & 1) * 16;
    const uint32_t qFrag = smb + QS_B + (warp * 16 + arow) * FROWB + abyte;

    auto load_kv = [&](int kt, int s) {
        const __half* Kb = K + base + (size_t)(kt * 64) * DIM;
        const __half* Vb = V + base + (size_t)(kt * 64) * DIM;
        const uint32_t ks = smb + KS_B(s);
        const uint32_t vs = smb + VS_B(s);
        #pragma unroll
        for (int p = 0; p < 2; ++p) {
            int slot = tid + p * 256;
            int row  = slot >> 3;
            int c8   = (slot & 7) * 8;
            CP_ASYNC16(ks + row * FROWB + c8 * 2, Kb + (size_t)row * DIM + c8);
            CP_ASYNC16(vs + row * FROWB + c8 * 2, Vb + (size_t)row * DIM + c8);
        }
        CP_COMMIT();
    };

    load_kv(0, 0);

    #pragma unroll
    for (int p = 0; p < 4; ++p) {
        int slot = tid + p * 256;
        int row  = slot >> 3;
        int c8   = (slot & 7) * 8;
        uint4 v = *reinterpret_cast<const uint4*>(
            &Q[base + (size_t)(q0 + row) * DIM + c8]);
        *reinterpret_cast<uint4*>(smc + QS_B + row * FROWB + c8 * 2) = v;
    }
    __syncthreads();

    unsigned qa[4][4];
    #pragma unroll
    for (int ks = 0; ks < 4; ++ks)
        LDSM_X4(qa[ks][0], qa[ks][1], qa[ks][2], qa[ks][3], qFrag + ks * 32);

    float m_i[2] = {-CUDART_INF_F, -CUDART_INF_F};
    float l_i[2] = {0.0f, 0.0f};
    float o[8][4];
    #pragma unroll
    for (int ni = 0; ni < 8; ++ni)
        #pragma unroll
        for (int j = 0; j < 4; ++j) o[ni][j] = 0.0f;

    const int row_loc = warp * 16 + r;
    const int ktmax   = 2 * qt + 1;

    for (int kt = 0; kt <= ktmax; ++kt) {
        const int s  = kt & 1;
        const int k0 = kt * 64;

        CP_WAIT(0);
        __syncthreads();
        if (kt < ktmax) load_kv(kt + 1, s ^ 1);

        const uint32_t kFrag = smb + KS_B(s) + brow * FROWB + bbyte;
        const uint32_t vFrag = smb + VS_B(s) + arow * FROWB + abyte;

        const bool active = (k0 <= q0 + warp * 16 + 15);
        if (active) {
            // ---- S = Q K^T ----
            float sreg[8][4];
            #pragma unroll
            for (int ni = 0; ni < 8; ++ni)
                #pragma unroll
                for (int j = 0; j < 4; ++j) sreg[ni][j] = 0.0f;

            #pragma unroll
            for (int ks = 0; ks < 4; ++ks) {
                #pragma unroll
                for (int pi = 0; pi < 4; ++pi) {
                    unsigned b0, b1, b2, b3;
                    LDSM_X4(b0, b1, b2, b3, kFrag + pi * (16 * FROWB) + ks * 32);
                    mma_f16(sreg[2*pi],   qa[ks][0], qa[ks][1], qa[ks][2], qa[ks][3], b0, b1);
                    mma_f16(sreg[2*pi+1], qa[ks][0], qa[ks][1], qa[ks][2], qa[ks][3], b2, b3);
                }
            }

            // ---- causal mask (diagonal tiles only) ----
            if (k0 + 63 > q0 + warp * 16) {
                const int rg0 = q0 + row_loc;
                #pragma unroll
                for (int ni = 0; ni < 8; ++ni) {
                    int cg = k0 + ni * 8 + 2 * t;
                    if (cg     > rg0    ) sreg[ni][0] = -CUDART_INF_F;
                    if (cg + 1 > rg0    ) sreg[ni][1] = -CUDART_INF_F;
                    if (cg     > rg0 + 8) sreg[ni][2] = -CUDART_INF_F;
                    if (cg + 1 > rg0 + 8) sreg[ni][3] = -CUDART_INF_F;
                }
            }

            // ---- base-2 online softmax (fp32 ex2, R8-proven) ----
            #pragma unroll
            for (int hh = 0; hh < 2; ++hh) {
                float mx = -CUDART_INF_F;
                #pragma unroll
                for (int ni = 0; ni < 8; ++ni)
                    mx = fmaxf(mx, fmaxf(sreg[ni][hh * 2], sreg[ni][hh * 2 + 1]));
                mx = fmaxf(mx, __shfl_xor_sync(0xffffffffu, mx, 1, 4));
                mx = fmaxf(mx, __shfl_xor_sync(0xffffffffu, mx, 2, 4));
                float mnew  = fmaxf(m_i[hh], mx);
                float alpha = ex2f(m_i[hh] - mnew);
                m_i[hh] = mnew;
                float rs = 0.0f;
                #pragma unroll
                for (int ni = 0; ni < 8; ++ni) {
                    float p0 = ex2f(sreg[ni][hh * 2]     - mnew);
                    float p1 = ex2f(sreg[ni][hh * 2 + 1] - mnew);
                    sreg[ni][hh * 2]     = p0;
                    sreg[ni][hh * 2 + 1] = p1;
                    rs += p0 + p1;
                }
                rs += __shfl_xor_sync(0xffffffffu, rs, 1, 4);
                rs += __shfl_xor_sync(0xffffffffu, rs, 2, 4);
                l_i[hh] = l_i[hh] * alpha + rs;
                #pragma unroll
                for (int ni = 0; ni < 8; ++ni) {
                    o[ni][hh * 2]     *= alpha;
                    o[ni][hh * 2 + 1] *= alpha;
                }
            }

            // ---- C-frag -> A-frag register conversion (no smem) ----
            unsigned pa[4][4];
            #pragma unroll
            for (int ks = 0; ks < 4; ++ks) {
                pa[ks][0] = pack_h2(sreg[2*ks][0],   sreg[2*ks][1]);
                pa[ks][1] = pack_h2(sreg[2*ks][2],   sreg[2*ks][3]);
                pa[ks][2] = pack_h2(sreg[2*ks+1][0], sreg[2*ks+1][1]);
                pa[ks][3] = pack_h2(sreg[2*ks+1][2], sreg[2*ks+1][3]);
            }

            // ---- O += P V  (V B-frags via ldmatrix.trans from [k][d]) ----
            #pragma unroll
            for (int ks = 0; ks < 4; ++ks) {
                #pragma unroll
                for (int pi = 0; pi < 4; ++pi) {
                    unsigned b0, b1, b2, b3;
                    LDSM_X4T(b0, b1, b2, b3,
                             vFrag + ks * (16 * FROWB) + pi * 32);
                    mma_f16(o[2*pi],   pa[ks][0], pa[ks][1], pa[ks][2], pa[ks][3], b0, b1);
                    mma_f16(o[2*pi+1], pa[ks][0], pa[ks][1], pa[ks][2], pa[ks][3], b2, b3);
                }
            }
        }
        // no tail barrier: next iteration's top-of-loop sync provides the
        // ordering before buffer 1-s is overwritten.
    }

    // ---- normalize + fp16 store ----
    #pragma unroll
    for (int hh = 0; hh < 2; ++hh) {
        float inv_l = 1.0f / l_i[hh];
        int row = q0 + row_loc + hh * 8;
        #pragma unroll
        for (int ni = 0; ni < 8; ++ni) {
            *reinterpret_cast<__half2*>(
                &O[base + (size_t)row * DIM + ni * 8 + 2 * t]) =
                __floats2half2_rn(o[ni][hh * 2] * inv_l, o[ni][hh * 2 + 1] * inv_l);
        }
    }
}

// ---------------------------------------------------------------------------
// Launch
// ---------------------------------------------------------------------------
extern "C" void kernel_launch(void* const* d_in, const int* in_sizes, int n_in,
                              void* d_out, int out_size)
{
    const float* x  = (const float*)d_in[0];
    const float* Wq = (const float*)d_in[2];
    const float* Wk = (const float*)d_in[3];
    const float* Wv = (const float*)d_in[4];
    const float* Wo = (const float*)d_in[5];
    float* out = (float*)d_out;

    __half *QKV, *AOd, *Xh, *Wh;
    cudaGetSymbolAddress((void**)&QKV, g_QKV);
    cudaGetSymbolAddress((void**)&AOd, g_AO);
    cudaGetSymbolAddress((void**)&Xh,  g_Xh);
    cudaGetSymbolAddress((void**)&Wh,  g_Wh);

    static bool attr_set = false;
    if (!attr_set) {
        cudaFuncSetAttribute(flash_f16,
                             cudaFuncAttributeMaxDynamicSharedMemorySize, FL_SMEMB);
        cudaFuncSetAttribute((gemm_f16<true, true>),
                             cudaFuncAttributeMaxDynamicSharedMemorySize, SMEM_GEMM);
        cudaFuncSetAttribute((gemm_f16<false, false>),
                             cudaFuncAttributeMaxDynamicSharedMemorySize, SMEM_GEMM);
        attr_set = true;
    }

    cvt_x_k<<<1024, 256>>>((const float4*)x, (__half2*)Xh, MTOT * DIM / 4);
    cvt_w_k<<<dim3(128, 4), 256>>>((const float4*)Wq, (const float4*)Wk,
                                   (const float4*)Wv, (const float4*)Wo, (__half2*)Wh);

    // fused Q,K,V projections; Q pre-scaled by 0.125*log2(e)
    dim3 gQKV(DIM / 128, MTOT / 128, 3);   // (8, 64, 3)
    gemm_f16<true, true><<<gQKV, 256, SMEM_GEMM>>>(Xh, Wh, QKV);

    const __half* Qd = QKV;
    const __half* Kd = QKV + (size_t)MTOT * DIM;
    const __half* Vd = QKV + 2 * (size_t)MTOT * DIM;

    dim3 gF(SEQ / 128, NHEAD, BATCH);      // (16, 16, 4)
    flash_f16<<<gF, 256, FL_SMEMB>>>(Qd, Kd, Vd, AOd);

    dim3 gO(DIM / 128, MTOT / 128, 1);     // (8, 64, 1)
    gemm_f16<false, false><<<gO, 256, SMEM_GEMM>>>(AOd, Wh + 3 * (size_t)DIM * DIM, out);
}

// round 12
// speedup vs baseline: 1.1769x; 1.0229x over previous
#include <cuda_runtime.h>
#include <cuda_fp16.h>
#include <math_constants.h>
#include <cstdint>

#define DIM    1024
#define NHEAD  16
#define HDIM   64
#define BATCH  4
#define SEQ    2048
#define MTOT   (BATCH * SEQ)      // 8192

// Q pre-scale: 64^-0.5 * log2(e)  (softmax done in base 2)
#define QSCALE 0.18033688011112042f

// ---------------------------------------------------------------------------
// Scratch (fp16 activations/weights)
// ---------------------------------------------------------------------------
__device__ __half g_QKV[3 * MTOT * DIM];   // Q(pre-scaled),K,V
__device__ __half g_AO [MTOT * DIM];       // attention out
__device__ __half g_Xh [MTOT * DIM];       // fp16 x
__device__ __half g_Wh [4 * DIM * DIM];    // fp16 Wq,Wk,Wv,Wo

// ---------------------------------------------------------------------------
// Helpers
// ---------------------------------------------------------------------------
__device__ __forceinline__ float ex2f(float x) {
    float y;
    asm("ex2.approx.f32 %0, %1;" : "=f"(y) : "f"(x));
    return y;
}

__device__ __forceinline__ uint32_t smem_u32(const void* p) {
    uint32_t a;
    asm("{ .reg .u64 t; cvta.to.shared.u64 t, %1; cvt.u32.u64 %0, t; }"
        : "=r"(a) : "l"(p));
    return a;
}

__device__ __forceinline__ unsigned pack_h2(float lo, float hi) {
    __half2 h = __floats2half2_rn(lo, hi);
    return *reinterpret_cast<unsigned*>(&h);
}

__device__ __forceinline__ void mma_f16(float* c,
                                        unsigned a0, unsigned a1,
                                        unsigned a2, unsigned a3,
                                        unsigned b0, unsigned b1) {
    asm volatile(
        "mma.sync.aligned.m16n8k16.row.col.f32.f16.f16.f32 "
        "{%0,%1,%2,%3},{%4,%5,%6,%7},{%8,%9},{%0,%1,%2,%3};\n"
        : "+f"(c[0]), "+f"(c[1]), "+f"(c[2]), "+f"(c[3])
        : "r"(a0), "r"(a1), "r"(a2), "r"(a3), "r"(b0), "r"(b1));
}

#define LDSM_X4(r0, r1, r2, r3, addr)                                         \
    asm volatile("ldmatrix.sync.aligned.m8n8.x4.shared.b16 {%0,%1,%2,%3}, [%4];" \
                 : "=r"(r0), "=r"(r1), "=r"(r2), "=r"(r3) : "r"(addr))

#define LDSM_X4T(r0, r1, r2, r3, addr)                                        \
    asm volatile("ldmatrix.sync.aligned.m8n8.x4.trans.shared.b16 {%0,%1,%2,%3}, [%4];" \
                 : "=r"(r0), "=r"(r1), "=r"(r2), "=r"(r3) : "r"(addr))

#define CP_ASYNC16(dst, src) \
    asm volatile("cp.async.cg.shared.global [%0], [%1], 16;" \
                 :: "r"(dst), "l"(src) : "memory")
#define CP_COMMIT() asm volatile("cp.async.commit_group;" ::: "memory")
#define CP_WAIT(N)  asm volatile("cp.async.wait_group %0;" :: "n"(N) : "memory")

// ---------------------------------------------------------------------------
// Pre-pass: fp32 -> fp16
// ---------------------------------------------------------------------------
__global__ void cvt_x_k(const float4* __restrict__ src,
                        __half2* __restrict__ dst, int n4)
{
    int i = blockIdx.x * blockDim.x + threadIdx.x;
    int stride = gridDim.x * blockDim.x;
    for (; i < n4; i += stride) {
        float4 v = src[i];
        dst[2 * i]     = __floats2half2_rn(v.x, v.y);
        dst[2 * i + 1] = __floats2half2_rn(v.z, v.w);
    }
}

__global__ void cvt_w_k(const float4* __restrict__ w0, const float4* __restrict__ w1,
                        const float4* __restrict__ w2, const float4* __restrict__ w3,
                        __half2* __restrict__ dst)
{
    const float4* src = (blockIdx.y == 0) ? w0 : (blockIdx.y == 1) ? w1
                       : (blockIdx.y == 2) ? w2 : w3;
    __half2* d = dst + (size_t)blockIdx.y * (DIM * DIM / 2);
    const int n4 = DIM * DIM / 4;
    int i = blockIdx.x * blockDim.x + threadIdx.x;
    int stride = gridDim.x * blockDim.x;
    for (; i < n4; i += stride) {
        float4 v = src[i];
        d[2 * i]     = __floats2half2_rn(v.x, v.y);
        d[2 * i + 1] = __floats2half2_rn(v.z, v.w);
    }
}

// ---------------------------------------------------------------------------
// FP16 GEMM: C = A * W^T. Tile 128(M) x 128(N), BK=64, 3-stage cp.async.
// 256 threads / 8 warps, warp tile 32x64, 2 blocks/SM.
// ---------------------------------------------------------------------------
#define BK      64
#define NCH     (DIM / BK)              // 16
#define GROWB   144
#define A_STGB  (128 * GROWB)           // 18432
#define STGB    (2 * A_STGB)            // 36864 (A + B)
#define SMEM_GEMM (3 * STGB)            // 110592

template<bool HALF_OUT, bool SCALEQ>
__global__ __launch_bounds__(256, 2)
void gemm_f16(const __half* __restrict__ Abase,
              const __half* __restrict__ Wbase,
              void* __restrict__ Cvoid)
{
    extern __shared__ char smc[];
    const uint32_t sbase = smem_u32(smc);

    const int tid  = threadIdx.x;
    const int lane = tid & 31;
    const int warp = tid >> 5;           // 0..7
    const int wm   = warp & 3;           // m offset wm*32
    const int wn   = warp >> 2;          // n offset wn*64
    const int r    = lane >> 2;
    const int t    = lane & 3;
    const int m0   = blockIdx.y * 128;
    const int n0   = blockIdx.x * 128;

    const __half* A = Abase;
    const __half* W = Wbase + (size_t)blockIdx.z * DIM * DIM;

    float c[2][8][4];
    #pragma unroll
    for (int mi = 0; mi < 2; ++mi)
        #pragma unroll
        for (int ni = 0; ni < 8; ++ni)
            #pragma unroll
            for (int j = 0; j < 4; ++j) c[mi][ni][j] = 0.0f;

    const int arow  = ((lane >> 3) & 1) * 8 + (lane & 7);
    const int abyte = (lane >> 4) * 16;
    const int brow  = ((lane >> 4) & 1) * 8 + (lane & 7);
    const int bbyte = ((lane >> 3) & 1) * 16;
    const uint32_t aFrag = (uint32_t)((wm * 32 + arow) * GROWB + abyte);
    const uint32_t bFrag = (uint32_t)(A_STGB + (wn * 64 + brow) * GROWB + bbyte);

    auto load_stage = [&](int ch, int s) {
        const __half* Ab = A + (size_t)m0 * DIM + ch * BK;
        const __half* Wb = W + (size_t)n0 * DIM + ch * BK;
        const uint32_t as = sbase + s * STGB;
        const uint32_t bs = as + A_STGB;
        #pragma unroll
        for (int p = 0; p < 4; ++p) {             // A: 1024 x 16B
            int slot = tid + p * 256;
            int row  = slot >> 3;
            int c8   = (slot & 7) * 8;
            CP_ASYNC16(as + row * GROWB + c8 * 2,
                       Ab + (size_t)row * DIM + c8);
        }
        #pragma unroll
        for (int p = 0; p < 4; ++p) {             // B: 1024 x 16B
            int slot = tid + p * 256;
            int row  = slot >> 3;
            int c8   = (slot & 7) * 8;
            CP_ASYNC16(bs + row * GROWB + c8 * 2,
                       Wb + (size_t)row * DIM + c8);
        }
        CP_COMMIT();
    };

    load_stage(0, 0);
    load_stage(1, 1);

    for (int ch = 0; ch < NCH; ++ch) {
        if (ch < NCH - 1) { CP_WAIT(1); } else { CP_WAIT(0); }
        __syncthreads();
        if (ch + 2 < NCH) load_stage(ch + 2, (ch + 2) % 3);

        const uint32_t stg = sbase + (ch % 3) * STGB;
        const uint32_t aB  = stg + aFrag;
        const uint32_t bB  = stg + bFrag;

        #pragma unroll
        for (int ks = 0; ks < 4; ++ks) {
            unsigned a[2][4], b[4][4];
            #pragma unroll
            for (int mi = 0; mi < 2; ++mi)
                LDSM_X4(a[mi][0], a[mi][1], a[mi][2], a[mi][3],
                        aB + mi * (16 * GROWB) + ks * 32);
            #pragma unroll
            for (int pi = 0; pi < 4; ++pi)
                LDSM_X4(b[pi][0], b[pi][1], b[pi][2], b[pi][3],
                        bB + pi * (16 * GROWB) + ks * 32);
            #pragma unroll
            for (int mi = 0; mi < 2; ++mi)
                #pragma unroll
                for (int pi = 0; pi < 4; ++pi) {
                    mma_f16(c[mi][2*pi],   a[mi][0], a[mi][1], a[mi][2], a[mi][3],
                            b[pi][0], b[pi][1]);
                    mma_f16(c[mi][2*pi+1], a[mi][0], a[mi][1], a[mi][2], a[mi][3],
                            b[pi][2], b[pi][3]);
                }
        }
    }

    const float sc = (SCALEQ && blockIdx.z == 0) ? QSCALE : 1.0f;
    #pragma unroll
    for (int mi = 0; mi < 2; ++mi) {
        #pragma unroll
        for (int ni = 0; ni < 8; ++ni) {
            int row = m0 + wm * 32 + mi * 16 + r;
            int col = n0 + wn * 64 + ni * 8 + 2 * t;
            float v0 = c[mi][ni][0] * sc, v1 = c[mi][ni][1] * sc;
            float v2 = c[mi][ni][2] * sc, v3 = c[mi][ni][3] * sc;
            if (HALF_OUT) {
                __half* C = (__half*)Cvoid + (size_t)blockIdx.z * MTOT * DIM;
                *reinterpret_cast<__half2*>(&C[(size_t)row * DIM + col]) =
                    __floats2half2_rn(v0, v1);
                *reinterpret_cast<__half2*>(&C[(size_t)(row + 8) * DIM + col]) =
                    __floats2half2_rn(v2, v3);
            } else {
                float* C = (float*)Cvoid;
                *reinterpret_cast<float2*>(&C[(size_t)row * DIM + col])       = make_float2(v0, v1);
                *reinterpret_cast<float2*>(&C[(size_t)(row + 8) * DIM + col]) = make_float2(v2, v3);
            }
        }
    }
}

// ---------------------------------------------------------------------------
// Flash attention, fp16, register-resident P, fp32-ex2 softmax.
// Q-tile 64 (4 warps / 128 threads), K-tile 64, K/V double-buffered cp.async.
// 4 blocks/SM -> 4 independent barrier domains (issue fills while a sibling
// block waits). Single barrier per iteration.
// ---------------------------------------------------------------------------
#define FROWB 144                               // 64 halves + 16B pad
#define QS_B  0
#define KS_B(s) (9216 + (s) * 9216)             // Q is 64 rows now (9216 B)
#define VS_B(s) (27648 + (s) * 9216)
#define FL_SMEMB 46080

__global__ __launch_bounds__(128, 4)
void flash_f16(const __half* __restrict__ Q,
               const __half* __restrict__ K,
               const __half* __restrict__ V,
               __half* __restrict__ O)
{
    extern __shared__ char smc[];
    const uint32_t smb = smem_u32(smc);

    const int tid  = threadIdx.x;
    const int lane = tid & 31;
    const int warp = tid >> 5;            // 0..3
    const int r    = lane >> 2;
    const int t    = lane & 3;
    const int qt   = (gridDim.x - 1) - blockIdx.x;   // heavy first
    const int h    = blockIdx.y;
    const int b    = blockIdx.z;
    const int q0   = qt * 64;
    const size_t base = (size_t)b * SEQ * DIM + (size_t)h * HDIM;

    const int arow  = ((lane >> 3) & 1) * 8 + (lane & 7);
    const int abyte = (lane >> 4) * 16;
    const int brow  = ((lane >> 4) & 1) * 8 + (lane & 7);
    const int bbyte = ((lane >> 3) & 1) * 16;
    const uint32_t qFrag = smb + QS_B + (warp * 16 + arow) * FROWB + abyte;

    auto load_kv = [&](int kt, int s) {
        const __half* Kb = K + base + (size_t)(kt * 64) * DIM;
        const __half* Vb = V + base + (size_t)(kt * 64) * DIM;
        const uint32_t ks = smb + KS_B(s);
        const uint32_t vs = smb + VS_B(s);
        #pragma unroll
        for (int p = 0; p < 4; ++p) {             // 512 x 16B each tile
            int slot = tid + p * 128;
            int row  = slot >> 3;
            int c8   = (slot & 7) * 8;
            CP_ASYNC16(ks + row * FROWB + c8 * 2, Kb + (size_t)row * DIM + c8);
            CP_ASYNC16(vs + row * FROWB + c8 * 2, Vb + (size_t)row * DIM + c8);
        }
        CP_COMMIT();
    };

    load_kv(0, 0);

    // Q tile: 64 rows x 8 chunks = 512 slots (4/thread)
    #pragma unroll
    for (int p = 0; p < 4; ++p) {
        int slot = tid + p * 128;
        int row  = slot >> 3;
        int c8   = (slot & 7) * 8;
        uint4 v = *reinterpret_cast<const uint4*>(
            &Q[base + (size_t)(q0 + row) * DIM + c8]);
        *reinterpret_cast<uint4*>(smc + QS_B + row * FROWB + c8 * 2) = v;
    }
    __syncthreads();

    unsigned qa[4][4];
    #pragma unroll
    for (int ks = 0; ks < 4; ++ks)
        LDSM_X4(qa[ks][0], qa[ks][1], qa[ks][2], qa[ks][3], qFrag + ks * 32);

    float m_i[2] = {-CUDART_INF_F, -CUDART_INF_F};
    float l_i[2] = {0.0f, 0.0f};
    float o[8][4];
    #pragma unroll
    for (int ni = 0; ni < 8; ++ni)
        #pragma unroll
        for (int j = 0; j < 4; ++j) o[ni][j] = 0.0f;

    const int row_loc = warp * 16 + r;
    const int ktmax   = qt;               // 64-row q-tile == 64-row kv-tile

    for (int kt = 0; kt <= ktmax; ++kt) {
        const int s  = kt & 1;
        const int k0 = kt * 64;

        CP_WAIT(0);
        __syncthreads();
        if (kt < ktmax) load_kv(kt + 1, s ^ 1);

        const uint32_t kFrag = smb + KS_B(s) + brow * FROWB + bbyte;
        const uint32_t vFrag = smb + VS_B(s) + arow * FROWB + abyte;

        // ---- S = Q K^T ----
        float sreg[8][4];
        #pragma unroll
        for (int ni = 0; ni < 8; ++ni)
            #pragma unroll
            for (int j = 0; j < 4; ++j) sreg[ni][j] = 0.0f;

        #pragma unroll
        for (int ks = 0; ks < 4; ++ks) {
            #pragma unroll
            for (int pi = 0; pi < 4; ++pi) {
                unsigned b0, b1, b2, b3;
                LDSM_X4(b0, b1, b2, b3, kFrag + pi * (16 * FROWB) + ks * 32);
                mma_f16(sreg[2*pi],   qa[ks][0], qa[ks][1], qa[ks][2], qa[ks][3], b0, b1);
                mma_f16(sreg[2*pi+1], qa[ks][0], qa[ks][1], qa[ks][2], qa[ks][3], b2, b3);
            }
        }

        // ---- causal mask (diagonal tile only) ----
        if (kt == ktmax) {
            const int rg0 = q0 + row_loc;
            #pragma unroll
            for (int ni = 0; ni < 8; ++ni) {
                int cg = k0 + ni * 8 + 2 * t;
                if (cg     > rg0    ) sreg[ni][0] = -CUDART_INF_F;
                if (cg + 1 > rg0    ) sreg[ni][1] = -CUDART_INF_F;
                if (cg     > rg0 + 8) sreg[ni][2] = -CUDART_INF_F;
                if (cg + 1 > rg0 + 8) sreg[ni][3] = -CUDART_INF_F;
            }
        }

        // ---- base-2 online softmax (fp32 ex2) ----
        #pragma unroll
        for (int hh = 0; hh < 2; ++hh) {
            float mx = -CUDART_INF_F;
            #pragma unroll
            for (int ni = 0; ni < 8; ++ni)
                mx = fmaxf(mx, fmaxf(sreg[ni][hh * 2], sreg[ni][hh * 2 + 1]));
            mx = fmaxf(mx, __shfl_xor_sync(0xffffffffu, mx, 1, 4));
            mx = fmaxf(mx, __shfl_xor_sync(0xffffffffu, mx, 2, 4));
            float mnew  = fmaxf(m_i[hh], mx);
            float alpha = ex2f(m_i[hh] - mnew);
            m_i[hh] = mnew;
            float rs = 0.0f;
            #pragma unroll
            for (int ni = 0; ni < 8; ++ni) {
                float p0 = ex2f(sreg[ni][hh * 2]     - mnew);
                float p1 = ex2f(sreg[ni][hh * 2 + 1] - mnew);
                sreg[ni][hh * 2]     = p0;
                sreg[ni][hh * 2 + 1] = p1;
                rs += p0 + p1;
            }
            rs += __shfl_xor_sync(0xffffffffu, rs, 1, 4);
            rs += __shfl_xor_sync(0xffffffffu, rs, 2, 4);
            l_i[hh] = l_i[hh] * alpha + rs;
            #pragma unroll
            for (int ni = 0; ni < 8; ++ni) {
                o[ni][hh * 2]     *= alpha;
                o[ni][hh * 2 + 1] *= alpha;
            }
        }

        // ---- C-frag -> A-frag register conversion (no smem) ----
        unsigned pa[4][4];
        #pragma unroll
        for (int ks = 0; ks < 4; ++ks) {
            pa[ks][0] = pack_h2(sreg[2*ks][0],   sreg[2*ks][1]);
            pa[ks][1] = pack_h2(sreg[2*ks][2],   sreg[2*ks][3]);
            pa[ks][2] = pack_h2(sreg[2*ks+1][0], sreg[2*ks+1][1]);
            pa[ks][3] = pack_h2(sreg[2*ks+1][2], sreg[2*ks+1][3]);
        }

        // ---- O += P V  (V B-frags via ldmatrix.trans from [k][d]) ----
        #pragma unroll
        for (int ks = 0; ks < 4; ++ks) {
            #pragma unroll
            for (int pi = 0; pi < 4; ++pi) {
                unsigned b0, b1, b2, b3;
                LDSM_X4T(b0, b1, b2, b3,
                         vFrag + ks * (16 * FROWB) + pi * 32);
                mma_f16(o[2*pi],   pa[ks][0], pa[ks][1], pa[ks][2], pa[ks][3], b0, b1);
                mma_f16(o[2*pi+1], pa[ks][0], pa[ks][1], pa[ks][2], pa[ks][3], b2, b3);
            }
        }
        // no tail barrier: next iteration's top-of-loop sync provides ordering
    }

    // ---- normalize + fp16 store ----
    #pragma unroll
    for (int hh = 0; hh < 2; ++hh) {
        float inv_l = 1.0f / l_i[hh];
        int row = q0 + row_loc + hh * 8;
        #pragma unroll
        for (int ni = 0; ni < 8; ++ni) {
            *reinterpret_cast<__half2*>(
                &O[base + (size_t)row * DIM + ni * 8 + 2 * t]) =
                __floats2half2_rn(o[ni][hh * 2] * inv_l, o[ni][hh * 2 + 1] * inv_l);
        }
    }
}

// ---------------------------------------------------------------------------
// Launch
// ---------------------------------------------------------------------------
extern "C" void kernel_launch(void* const* d_in, const int* in_sizes, int n_in,
                              void* d_out, int out_size)
{
    const float* x  = (const float*)d_in[0];
    const float* Wq = (const float*)d_in[2];
    const float* Wk = (const float*)d_in[3];
    const float* Wv = (const float*)d_in[4];
    const float* Wo = (const float*)d_in[5];
    float* out = (float*)d_out;

    __half *QKV, *AOd, *Xh, *Wh;
    cudaGetSymbolAddress((void**)&QKV, g_QKV);
    cudaGetSymbolAddress((void**)&AOd, g_AO);
    cudaGetSymbolAddress((void**)&Xh,  g_Xh);
    cudaGetSymbolAddress((void**)&Wh,  g_Wh);

    static bool attr_set = false;
    if (!attr_set) {
        cudaFuncSetAttribute(flash_f16,
                             cudaFuncAttributeMaxDynamicSharedMemorySize, FL_SMEMB);
        cudaFuncSetAttribute((gemm_f16<true, true>),
                             cudaFuncAttributeMaxDynamicSharedMemorySize, SMEM_GEMM);
        cudaFuncSetAttribute((gemm_f16<false, false>),
                             cudaFuncAttributeMaxDynamicSharedMemorySize, SMEM_GEMM);
        attr_set = true;
    }

    cvt_x_k<<<1024, 256>>>((const float4*)x, (__half2*)Xh, MTOT * DIM / 4);
    cvt_w_k<<<dim3(128, 4), 256>>>((const float4*)Wq, (const float4*)Wk,
                                   (const float4*)Wv, (const float4*)Wo, (__half2*)Wh);

    // fused Q,K,V projections; Q pre-scaled by 0.125*log2(e)
    dim3 gQKV(DIM / 128, MTOT / 128, 3);   // (8, 64, 3)
    gemm_f16<true, true><<<gQKV, 256, SMEM_GEMM>>>(Xh, Wh, QKV);

    const __half* Qd = QKV;
    const __half* Kd = QKV + (size_t)MTOT * DIM;
    const __half* Vd = QKV + 2 * (size_t)MTOT * DIM;

    dim3 gF(SEQ / 64, NHEAD, BATCH);       // (32, 16, 4)
    flash_f16<<<gF, 128, FL_SMEMB>>>(Qd, Kd, Vd, AOd);

    dim3 gO(DIM / 128, MTOT / 128, 1);     // (8, 64, 1)
    gemm_f16<false, false><<<gO, 256, SMEM_GEMM>>>(AOd, Wh + 3 * (size_t)DIM * DIM, out);
}